// round 3
// baseline (speedup 1.0000x reference)
#include <cuda_runtime.h>
#include <cuda_bf16.h>

// Problem constants
#define T_STEPS 4
#define BATCH   64
#define CIN     64
#define COUT    128
#define HH      32
#define WW      32
#define TAU     0.5f
#define THRESH  1.0f
#define BN_EPS  1e-5f

// Scratch: transposed weights [cin*9][cout] + folded BN affine
__device__ float g_wT[CIN * 9 * COUT];
__device__ float g_alpha[COUT];
__device__ float g_beta[COUT];

// ---------- f32x2 packed helpers ----------
__device__ __forceinline__ void unpack2(unsigned long long v, float& lo, float& hi) {
    asm("mov.b64 {%0, %1}, %2;" : "=f"(lo), "=f"(hi) : "l"(v));
}
__device__ __forceinline__ void ffma2(unsigned long long& d,
                                      unsigned long long a,
                                      unsigned long long b) {
    asm("fma.rn.f32x2 %0, %1, %2, %3;" : "=l"(d) : "l"(a), "l"(b), "l"(d));
}

// ---------- prep: weight transpose + BN fold ----------
__global__ void prep_kernel(const float* __restrict__ w,
                            const float* __restrict__ cb,
                            const float* __restrict__ gamma,
                            const float* __restrict__ beta,
                            const float* __restrict__ mean,
                            const float* __restrict__ var) {
    int idx = blockIdx.x * blockDim.x + threadIdx.x;
    int stride = gridDim.x * blockDim.x;
    // wT[r][co] = w[co][r], r = cin*9 + k (k = kh*3+kw)
    for (int i = idx; i < CIN * 9 * COUT; i += stride) {
        int co = i & (COUT - 1);
        int r  = i >> 7;           // / COUT
        g_wT[i] = w[co * (CIN * 9) + r];
    }
    if (idx < COUT) {
        float inv = rsqrtf(var[idx] + BN_EPS);
        float sc  = gamma[idx] * inv;
        g_alpha[idx] = sc;
        g_beta[idx] = beta[idx] - mean[idx] * sc + cb[idx] * sc;
    }
}

// ---------- fused conv3x3 + BN + LIF ----------
// Grid: (B, COUT/32, HH/8). Block: 256 threads.
// Thread tile: 8 couts (4 f32x2 pairs) x 4 pixels (1 row, 4 consecutive w).
// x held in smem as DUPLICATED float2 pairs in transposed [ci][w (34)][h (10)]
// layout: pair index = ci*340 + w*10 + h.  GEMM-phase LDS.64 reads are then
// conflict-free with thread map h=tid&7, w_grp=(tid>>3)&7 (h contributes 8B
// contiguous, w_grp contributes +320B == 64 mod 128).
#define CIN_CHUNK 16
#define SXD_PAIRS (CIN_CHUNK * 34 * 10)          // 5440 float2 = 43520 B
#define SW_FLOATS (CIN_CHUNK * 9 * 32)           // 4608 floats = 18432 B
#define SMEM_BYTES (SXD_PAIRS * 8 + SW_FLOATS * 4)   // 61952 B

__global__ __launch_bounds__(256, 2)
void conv_lif_kernel(const float* __restrict__ x, float* __restrict__ out) {
    extern __shared__ __align__(16) float smem_dyn[];
    float2* sxd = reinterpret_cast<float2*>(smem_dyn);            // dup x
    float*  sw  = smem_dyn + SXD_PAIRS * 2;                       // weights

    const int b     = blockIdx.x;
    const int cout0 = blockIdx.y * 32;
    const int h0    = blockIdx.z * 8;

    const int tid    = threadIdx.x;
    const int h_loc  = tid & 7;          // 8 rows     (NOTE: swapped vs R1)
    const int w_grp  = (tid >> 3) & 7;   // 8 groups of 4 w-pixels
    const int co_grp = tid >> 6;         // 4 groups of 8 couts
    const int w0     = w_grp * 4;
    const int myc0   = cout0 + co_grp * 8;

    const int xbase  = w0 * 10 + h_loc;  // thread-invariant part of x pair idx
    const int wbase  = co_grp * 8;

    float alpha[8], betav[8];
#pragma unroll
    for (int i = 0; i < 8; i++) {
        alpha[i] = g_alpha[myc0 + i];
        betav[i] = g_beta[myc0 + i];
    }

    float mem[8][4];
#pragma unroll
    for (int c = 0; c < 8; c++)
#pragma unroll
        for (int p = 0; p < 4; p++) mem[c][p] = 0.f;

    for (int t = 0; t < T_STEPS; t++) {
        unsigned long long acc[4][4];
#pragma unroll
        for (int cp = 0; cp < 4; cp++)
#pragma unroll
            for (int p = 0; p < 4; p++) acc[cp][p] = 0ULL;

        for (int c0 = 0; c0 < CIN; c0 += CIN_CHUNK) {
            __syncthreads();  // previous chunk's smem reads complete

            // ---- load x tile: duplicated pairs, transposed [ci][w][h] ----
            const float* xb = x + (((t * BATCH + b) * CIN + c0) * (HH * WW));
            for (int e = tid; e < CIN_CHUNK * 10 * 34; e += 256) {
                int ci  = e / 340;
                int rem = e - ci * 340;
                int r   = rem / 34;           // smem h index 0..9
                int c   = rem - r * 34;       // smem w index 0..33
                int gh  = h0 - 1 + r;
                int gw  = c - 1;
                float v = 0.f;
                if ((unsigned)gh < (unsigned)HH && (unsigned)gw < (unsigned)WW)
                    v = xb[ci * (HH * WW) + gh * WW + gw];
                sxd[ci * 340 + c * 10 + r] = make_float2(v, v);
            }

            // ---- load weight tile (vectorized, coalesced both sides) ----
            {
                const float* wb = g_wT + c0 * 9 * COUT + cout0;
                for (int e = tid; e < CIN_CHUNK * 9 * 8; e += 256) {
                    int co4 = e & 7;          // group of 4 couts
                    int rk  = e >> 3;         // ci*9 + k
                    float4 v = *reinterpret_cast<const float4*>(wb + rk * COUT + co4 * 4);
                    *reinterpret_cast<float4*>(sw + rk * 32 + co4 * 4) = v;
                }
            }
            __syncthreads();

            // ---- main accumulation ----
#pragma unroll 2
            for (int ci = 0; ci < CIN_CHUNK; ci++) {
                const float2* xcol = sxd + ci * 340 + xbase;
                const float*  wrow = sw + (ci * 9) * 32 + wbase;
#pragma unroll
                for (int kh = 0; kh < 3; kh++) {
                    unsigned long long xq[6];
#pragma unroll
                    for (int k = 0; k < 6; k++)
                        xq[k] = *reinterpret_cast<const unsigned long long*>(
                            xcol + k * 10 + kh);
#pragma unroll
                    for (int kw = 0; kw < 3; kw++) {
                        const ulonglong2* wp = reinterpret_cast<const ulonglong2*>(
                            wrow + (kh * 3 + kw) * 32);
                        ulonglong2 wA = wp[0];
                        ulonglong2 wB = wp[1];
                        unsigned long long wq0 = wA.x, wq1 = wA.y,
                                           wq2 = wB.x, wq3 = wB.y;
#pragma unroll
                        for (int p = 0; p < 4; p++) {
                            ffma2(acc[0][p], wq0, xq[kw + p]);
                            ffma2(acc[1][p], wq1, xq[kw + p]);
                            ffma2(acc[2][p], wq2, xq[kw + p]);
                            ffma2(acc[3][p], wq3, xq[kw + p]);
                        }
                    }
                }
            }
        }

        // ---- epilogue: BN affine + LIF update + spike store ----
        float* ob = out + ((size_t)(t * BATCH + b) * COUT) * (HH * WW)
                        + (h0 + h_loc) * WW + w0;
#pragma unroll
        for (int cp = 0; cp < 4; cp++) {
            const int cl0 = 2 * cp, cl1 = 2 * cp + 1;
            float sp0[4], sp1[4];
#pragma unroll
            for (int p = 0; p < 4; p++) {
                float lo, hi;
                unpack2(acc[cp][p], lo, hi);
                float y0 = lo * alpha[cl0] + betav[cl0];
                float y1 = hi * alpha[cl1] + betav[cl1];
                float m0 = mem[cl0][p] * TAU + y0;
                float m1 = mem[cl1][p] * TAU + y1;
                float k0 = (m0 > THRESH) ? 1.f : 0.f;
                float k1 = (m1 > THRESH) ? 1.f : 0.f;
                mem[cl0][p] = (k0 != 0.f) ? 0.f : m0;  // hard reset
                mem[cl1][p] = (k1 != 0.f) ? 0.f : m1;
                sp0[p] = k0;
                sp1[p] = k1;
            }
            *reinterpret_cast<float4*>(ob + (size_t)(myc0 + cl0) * (HH * WW)) =
                make_float4(sp0[0], sp0[1], sp0[2], sp0[3]);
            *reinterpret_cast<float4*>(ob + (size_t)(myc0 + cl1) * (HH * WW)) =
                make_float4(sp1[0], sp1[1], sp1[2], sp1[3]);
        }
    }
}

extern "C" void kernel_launch(void* const* d_in, const int* in_sizes, int n_in,
                              void* d_out, int out_size) {
    (void)in_sizes; (void)n_in; (void)out_size;
    const float* x      = (const float*)d_in[0];
    const float* conv_w = (const float*)d_in[1];
    const float* conv_b = (const float*)d_in[2];
    const float* bng    = (const float*)d_in[3];
    const float* bnb    = (const float*)d_in[4];
    const float* bnm    = (const float*)d_in[5];
    const float* bnv    = (const float*)d_in[6];
    float* out = (float*)d_out;

    // >48KB static limit -> dynamic smem (attribute set is idempotent & capture-safe)
    static int attr_done = 0;
    if (!attr_done) {
        cudaFuncSetAttribute(conv_lif_kernel,
                             cudaFuncAttributeMaxDynamicSharedMemorySize,
                             SMEM_BYTES);
        attr_done = 1;
    }

    prep_kernel<<<72, 256>>>(conv_w, conv_b, bng, bnb, bnm, bnv);

    dim3 grid(BATCH, COUT / 32, HH / 8);
    conv_lif_kernel<<<grid, 256, SMEM_BYTES>>>(x, out);
}

// round 4
// speedup vs baseline: 1.2450x; 1.2450x over previous
#include <cuda_runtime.h>
#include <cuda_bf16.h>

// Problem constants
#define T_STEPS 4
#define BATCH   64
#define CIN     64
#define COUT    128
#define HH      32
#define WW      32
#define TAU     0.5f
#define THRESH  1.0f
#define BN_EPS  1e-5f

// Scratch: transposed weights [cin*9][cout] + folded BN affine
__device__ float g_wT[CIN * 9 * COUT];
__device__ float g_alpha[COUT];
__device__ float g_beta[COUT];

// ---------- f32x2 packed helpers ----------
__device__ __forceinline__ unsigned long long pack2(float lo, float hi) {
    unsigned long long r;
    asm("mov.b64 %0, {%1, %2};" : "=l"(r) : "f"(lo), "f"(hi));
    return r;
}
__device__ __forceinline__ void unpack2(unsigned long long v, float& lo, float& hi) {
    asm("mov.b64 {%0, %1}, %2;" : "=f"(lo), "=f"(hi) : "l"(v));
}
__device__ __forceinline__ void ffma2(unsigned long long& d,
                                      unsigned long long a,
                                      unsigned long long b) {
    asm("fma.rn.f32x2 %0, %1, %2, %3;" : "=l"(d) : "l"(a), "l"(b), "l"(d));
}

// ---------- cp.async helpers ----------
__device__ __forceinline__ void cp_async4(unsigned dst, const void* src, int bytes) {
    asm volatile("cp.async.ca.shared.global [%0], [%1], 4, %2;"
                 :: "r"(dst), "l"(src), "r"(bytes));
}
__device__ __forceinline__ void cp_async16(unsigned dst, const void* src) {
    asm volatile("cp.async.cg.shared.global [%0], [%1], 16;"
                 :: "r"(dst), "l"(src));
}
#define CP_COMMIT()  asm volatile("cp.async.commit_group;" ::: "memory")
#define CP_WAIT_1()  asm volatile("cp.async.wait_group 1;" ::: "memory")
#define CP_WAIT_0()  asm volatile("cp.async.wait_group 0;" ::: "memory")

// ---------- prep: weight transpose + BN fold ----------
__global__ void prep_kernel(const float* __restrict__ w,
                            const float* __restrict__ cb,
                            const float* __restrict__ gamma,
                            const float* __restrict__ beta,
                            const float* __restrict__ mean,
                            const float* __restrict__ var) {
    int idx = blockIdx.x * blockDim.x + threadIdx.x;
    int stride = gridDim.x * blockDim.x;
    for (int i = idx; i < CIN * 9 * COUT; i += stride) {
        int co = i & (COUT - 1);
        int r  = i >> 7;
        g_wT[i] = w[co * (CIN * 9) + r];
    }
    if (idx < COUT) {
        float inv = rsqrtf(var[idx] + BN_EPS);
        float sc  = gamma[idx] * inv;
        g_alpha[idx] = sc;
        g_beta[idx]  = beta[idx] - mean[idx] * sc + cb[idx] * sc;
    }
}

// ---------- fused conv3x3 + BN + LIF, cp.async double-buffered ----------
// Grid: (B, COUT/32, HH/8). Block: 256 threads, 2 CTAs/SM.
// Thread tile: 8 couts (4 f32x2 pairs) x 4 pixels. R1-identical compute loop.
#define CIN_CHUNK 16
#define SX_ROWS   10
#define SX_PITCH  36
#define SX_FLOATS (CIN_CHUNK * SX_ROWS * SX_PITCH)   // 5760
#define SW_FLOATS (CIN_CHUNK * 9 * 32)               // 4608
#define BUF_FLOATS (SX_FLOATS + SW_FLOATS)           // 10368
#define SMEM_BYTES (2 * BUF_FLOATS * 4)              // 82944

#define N_CHUNKS (T_STEPS * (CIN / CIN_CHUNK))       // 16

__global__ __launch_bounds__(256, 2)
void conv_lif_kernel(const float* __restrict__ x, float* __restrict__ out) {
    extern __shared__ __align__(16) float smem_dyn[];

    const int b     = blockIdx.x;
    const int cout0 = blockIdx.y * 32;
    const int h0    = blockIdx.z * 8;

    const int tid    = threadIdx.x;
    const int w_grp  = tid & 7;
    const int h_loc  = (tid >> 3) & 7;
    const int co_grp = tid >> 6;
    const int w0     = w_grp * 4;
    const int myc0   = cout0 + co_grp * 8;

    const unsigned smem_u32 =
        (unsigned)__cvta_generic_to_shared(smem_dyn);

    // ---- prefetch lambda-equivalent (macro-ish inline) ----
    // chunk tc: t = tc>>2, c0 = (tc&3)*16; target buffer buf = tc&1
    auto prefetch = [&](int tc) {
        const int t  = tc >> 2;
        const int c0 = (tc & 3) * CIN_CHUNK;
        const int buf = tc & 1;
        const unsigned sx_base = smem_u32 + (unsigned)(buf * BUF_FLOATS) * 4u;
        const unsigned sw_base = sx_base + SX_FLOATS * 4u;
        const float* xb = x + (((t * BATCH + b) * CIN + c0) * (HH * WW));
        // x tile: 16*10*34 = 5440 elems, 4B cp.async with zfill for halo
        for (int e = tid; e < CIN_CHUNK * SX_ROWS * 34; e += 256) {
            int ci  = e / (SX_ROWS * 34);
            int rem = e - ci * (SX_ROWS * 34);
            int r   = rem / 34;
            int c   = rem - r * 34;
            int gh  = h0 - 1 + r;
            int gw  = c - 1;
            bool valid = ((unsigned)gh < (unsigned)HH) && ((unsigned)gw < (unsigned)WW);
            const float* src = valid ? (xb + ci * (HH * WW) + gh * WW + gw) : xb;
            unsigned dst = sx_base +
                (unsigned)(ci * (SX_ROWS * SX_PITCH) + r * SX_PITCH + c) * 4u;
            cp_async4(dst, src, valid ? 4 : 0);
        }
        // weights: 4608 floats = 1152 float4
        const float* wb = g_wT + c0 * 9 * COUT + cout0;
        for (int e = tid; e < SW_FLOATS / 4; e += 256) {
            int co4 = e & 7;
            int rk  = e >> 3;
            unsigned dst = sw_base + (unsigned)(rk * 32 + co4 * 4) * 4u;
            cp_async16(dst, wb + rk * COUT + co4 * 4);
        }
    };

    float alpha[8], betav[8];
#pragma unroll
    for (int i = 0; i < 8; i++) {
        alpha[i] = g_alpha[myc0 + i];
        betav[i] = g_beta[myc0 + i];
    }

    float mem[8][4];
#pragma unroll
    for (int c = 0; c < 8; c++)
#pragma unroll
        for (int p = 0; p < 4; p++) mem[c][p] = 0.f;

    unsigned long long acc[4][4];
#pragma unroll
    for (int cp = 0; cp < 4; cp++)
#pragma unroll
        for (int p = 0; p < 4; p++) acc[cp][p] = 0ULL;

    // prime the pipeline
    prefetch(0);
    CP_COMMIT();

    for (int tc = 0; tc < N_CHUNKS; tc++) {
        const int buf = tc & 1;
        float* sx = smem_dyn + buf * BUF_FLOATS;
        float* sw = sx + SX_FLOATS;

        if (tc + 1 < N_CHUNKS) {
            prefetch(tc + 1);
            CP_COMMIT();
            CP_WAIT_1();
        } else {
            CP_WAIT_0();
        }
        __syncthreads();   // chunk tc data visible to all warps

        // ---- main accumulation (identical order to R1) ----
        for (int ci = 0; ci < CIN_CHUNK; ci++) {
#pragma unroll
            for (int kh = 0; kh < 3; kh++) {
                const float* xr =
                    &sx[ci * (SX_ROWS * SX_PITCH) + (h_loc + kh) * SX_PITCH + w0];
                float4 xa = *reinterpret_cast<const float4*>(xr);
                float2 xc = *reinterpret_cast<const float2*>(xr + 4);
                unsigned long long xd[6];
                xd[0] = pack2(xa.x, xa.x);
                xd[1] = pack2(xa.y, xa.y);
                xd[2] = pack2(xa.z, xa.z);
                xd[3] = pack2(xa.w, xa.w);
                xd[4] = pack2(xc.x, xc.x);
                xd[5] = pack2(xc.y, xc.y);
#pragma unroll
                for (int kw = 0; kw < 3; kw++) {
                    const ulonglong2* wp = reinterpret_cast<const ulonglong2*>(
                        &sw[(ci * 9 + kh * 3 + kw) * 32 + co_grp * 8]);
                    ulonglong2 wA = wp[0];
                    ulonglong2 wB = wp[1];
                    unsigned long long wq0 = wA.x, wq1 = wA.y,
                                       wq2 = wB.x, wq3 = wB.y;
#pragma unroll
                    for (int p = 0; p < 4; p++) {
                        ffma2(acc[0][p], wq0, xd[kw + p]);
                        ffma2(acc[1][p], wq1, xd[kw + p]);
                        ffma2(acc[2][p], wq2, xd[kw + p]);
                        ffma2(acc[3][p], wq3, xd[kw + p]);
                    }
                }
            }
        }

        // ---- epilogue at the end of each t-step ----
        if ((tc & 3) == 3) {
            const int t = tc >> 2;
            float* ob = out + ((size_t)(t * BATCH + b) * COUT) * (HH * WW)
                            + (h0 + h_loc) * WW + w0;
#pragma unroll
            for (int cp = 0; cp < 4; cp++) {
                const int cl0 = 2 * cp, cl1 = 2 * cp + 1;
                float sp0[4], sp1[4];
#pragma unroll
                for (int p = 0; p < 4; p++) {
                    float lo, hi;
                    unpack2(acc[cp][p], lo, hi);
                    float y0 = lo * alpha[cl0] + betav[cl0];
                    float y1 = hi * alpha[cl1] + betav[cl1];
                    float m0 = mem[cl0][p] * TAU + y0;
                    float m1 = mem[cl1][p] * TAU + y1;
                    float k0 = (m0 > THRESH) ? 1.f : 0.f;
                    float k1 = (m1 > THRESH) ? 1.f : 0.f;
                    mem[cl0][p] = (k0 != 0.f) ? 0.f : m0;
                    mem[cl1][p] = (k1 != 0.f) ? 0.f : m1;
                    sp0[p] = k0;
                    sp1[p] = k1;
                }
                *reinterpret_cast<float4*>(ob + (size_t)(myc0 + cl0) * (HH * WW)) =
                    make_float4(sp0[0], sp0[1], sp0[2], sp0[3]);
                *reinterpret_cast<float4*>(ob + (size_t)(myc0 + cl1) * (HH * WW)) =
                    make_float4(sp1[0], sp1[1], sp1[2], sp1[3]);
            }
            // reset accumulators for next t
#pragma unroll
            for (int cp = 0; cp < 4; cp++)
#pragma unroll
                for (int p = 0; p < 4; p++) acc[cp][p] = 0ULL;
        }

        __syncthreads();   // all reads of buf done before it is re-prefetched
    }
}

extern "C" void kernel_launch(void* const* d_in, const int* in_sizes, int n_in,
                              void* d_out, int out_size) {
    (void)in_sizes; (void)n_in; (void)out_size;
    const float* x      = (const float*)d_in[0];
    const float* conv_w = (const float*)d_in[1];
    const float* conv_b = (const float*)d_in[2];
    const float* bng    = (const float*)d_in[3];
    const float* bnb    = (const float*)d_in[4];
    const float* bnm    = (const float*)d_in[5];
    const float* bnv    = (const float*)d_in[6];
    float* out = (float*)d_out;

    static int attr_done = 0;
    if (!attr_done) {
        cudaFuncSetAttribute(conv_lif_kernel,
                             cudaFuncAttributeMaxDynamicSharedMemorySize,
                             SMEM_BYTES);
        attr_done = 1;
    }

    prep_kernel<<<72, 256>>>(conv_w, conv_b, bng, bnb, bnm, bnv);

    dim3 grid(BATCH, COUT / 32, HH / 8);
    conv_lif_kernel<<<grid, 256, SMEM_BYTES>>>(x, out);
}

// round 5
// speedup vs baseline: 1.2586x; 1.0110x over previous
#include <cuda_runtime.h>
#include <cuda_bf16.h>

// Problem constants
#define T_STEPS 4
#define BATCH   64
#define CIN     64
#define COUT    128
#define HH      32
#define WW      32
#define TAU     0.5f
#define THRESH  1.0f
#define BN_EPS  1e-5f

// Scratch: transposed weights [cin*9][cout] + folded BN affine
__device__ float g_wT[CIN * 9 * COUT];
__device__ float g_alpha[COUT];
__device__ float g_beta[COUT];

// ---------- f32x2 packed helpers ----------
__device__ __forceinline__ unsigned long long pack2(float lo, float hi) {
    unsigned long long r;
    asm("mov.b64 %0, {%1, %2};" : "=l"(r) : "f"(lo), "f"(hi));
    return r;
}
__device__ __forceinline__ void unpack2(unsigned long long v, float& lo, float& hi) {
    asm("mov.b64 {%0, %1}, %2;" : "=f"(lo), "=f"(hi) : "l"(v));
}
__device__ __forceinline__ void ffma2(unsigned long long& d,
                                      unsigned long long a,
                                      unsigned long long b) {
    asm("fma.rn.f32x2 %0, %1, %2, %3;" : "=l"(d) : "l"(a), "l"(b), "l"(d));
}

// ---------- cp.async helpers ----------
__device__ __forceinline__ void cp_async4(unsigned dst, const void* src, int bytes) {
    asm volatile("cp.async.ca.shared.global [%0], [%1], 4, %2;"
                 :: "r"(dst), "l"(src), "r"(bytes));
}
__device__ __forceinline__ void cp_async16(unsigned dst, const void* src) {
    asm volatile("cp.async.cg.shared.global [%0], [%1], 16;"
                 :: "r"(dst), "l"(src));
}
#define CP_COMMIT()  asm volatile("cp.async.commit_group;" ::: "memory")
#define CP_WAIT_1()  asm volatile("cp.async.wait_group 1;" ::: "memory")
#define CP_WAIT_0()  asm volatile("cp.async.wait_group 0;" ::: "memory")

// ---------- prep: weight transpose + BN fold ----------
__global__ void prep_kernel(const float* __restrict__ w,
                            const float* __restrict__ cb,
                            const float* __restrict__ gamma,
                            const float* __restrict__ beta,
                            const float* __restrict__ mean,
                            const float* __restrict__ var) {
    int idx = blockIdx.x * blockDim.x + threadIdx.x;
    int stride = gridDim.x * blockDim.x;
    for (int i = idx; i < CIN * 9 * COUT; i += stride) {
        int co = i & (COUT - 1);
        int r  = i >> 7;
        g_wT[i] = w[co * (CIN * 9) + r];
    }
    if (idx < COUT) {
        float inv = rsqrtf(var[idx] + BN_EPS);
        float sc  = gamma[idx] * inv;
        g_alpha[idx] = sc;
        g_beta[idx]  = beta[idx] - mean[idx] * sc + cb[idx] * sc;
    }
}

// ---------- fused conv3x3 + BN + LIF, double-buffered, work-packed ----------
// 1024 logical tiles = (b:64) x (cout/32:4) x (h/8:4).
// Grid = 888 CTAs (3 exact waves of 296): bids < 136 process tiles {bid, bid+888}
// (heavy CTAs scheduled first in wave 1), others one tile. Chunk pipeline is
// linearized across a CTA's tiles so cp.async prefetch never drains.
#define CIN_CHUNK 16
#define SX_ROWS   10
#define SX_PITCH  36
#define SX_FLOATS (CIN_CHUNK * SX_ROWS * SX_PITCH)   // 5760
#define SW_FLOATS (CIN_CHUNK * 9 * 32)               // 4608
#define BUF_FLOATS (SX_FLOATS + SW_FLOATS)           // 10368
#define SMEM_BYTES (2 * BUF_FLOATS * 4)              // 82944

#define N_CHUNKS_PER_TILE (T_STEPS * (CIN / CIN_CHUNK))   // 16
#define N_TILES  (BATCH * (COUT / 32) * (HH / 8))         // 1024
#define GRID_CTAS 888
#define EXTRA_CTAS (N_TILES - GRID_CTAS)                  // 136

__device__ __forceinline__ void decode_tile(int tile_id, int& b, int& cout0, int& h0) {
    b     = tile_id >> 4;
    int r = tile_id & 15;
    cout0 = (r >> 2) * 32;
    h0    = (r & 3) * 8;
}

__global__ __launch_bounds__(256, 2)
void conv_lif_kernel(const float* __restrict__ x, float* __restrict__ out) {
    extern __shared__ __align__(16) float smem_dyn[];

    const int bid = blockIdx.x;
    const int ntiles = (bid < EXTRA_CTAS) ? 2 : 1;
    const int n_gc = ntiles * N_CHUNKS_PER_TILE;

    const int tid    = threadIdx.x;
    const int w_grp  = tid & 7;
    const int h_loc  = (tid >> 3) & 7;
    const int co_grp = tid >> 6;
    const int w0     = w_grp * 4;

    const unsigned smem_u32 = (unsigned)__cvta_generic_to_shared(smem_dyn);

    // prefetch global chunk gc: tile = gc>>4 (0 -> bid, 1 -> bid+GRID),
    // tc = gc&15, t = tc>>2, c0 = (tc&3)*16, dest buffer = gc&1
    auto prefetch = [&](int gc) {
        const int tile_id = (gc >> 4) ? (bid + GRID_CTAS) : bid;
        int b, cout0, h0;
        decode_tile(tile_id, b, cout0, h0);
        const int tc = gc & 15;
        const int t  = tc >> 2;
        const int c0 = (tc & 3) * CIN_CHUNK;
        const int buf = gc & 1;
        const unsigned sx_base = smem_u32 + (unsigned)(buf * BUF_FLOATS) * 4u;
        const unsigned sw_base = sx_base + SX_FLOATS * 4u;
        const float* xb = x + (((t * BATCH + b) * CIN + c0) * (HH * WW));
        for (int e = tid; e < CIN_CHUNK * SX_ROWS * 34; e += 256) {
            int ci  = e / (SX_ROWS * 34);
            int rem = e - ci * (SX_ROWS * 34);
            int r   = rem / 34;
            int c   = rem - r * 34;
            int gh  = h0 - 1 + r;
            int gw  = c - 1;
            bool valid = ((unsigned)gh < (unsigned)HH) && ((unsigned)gw < (unsigned)WW);
            const float* src = valid ? (xb + ci * (HH * WW) + gh * WW + gw) : xb;
            unsigned dst = sx_base +
                (unsigned)(ci * (SX_ROWS * SX_PITCH) + r * SX_PITCH + c) * 4u;
            cp_async4(dst, src, valid ? 4 : 0);
        }
        const float* wb = g_wT + c0 * 9 * COUT + cout0;
        for (int e = tid; e < SW_FLOATS / 4; e += 256) {
            int co4 = e & 7;
            int rk  = e >> 3;
            unsigned dst = sw_base + (unsigned)(rk * 32 + co4 * 4) * 4u;
            cp_async16(dst, wb + rk * COUT + co4 * 4);
        }
    };

    float mem[8][4];
#pragma unroll
    for (int c = 0; c < 8; c++)
#pragma unroll
        for (int p = 0; p < 4; p++) mem[c][p] = 0.f;

    unsigned long long acc[4][4];
#pragma unroll
    for (int cp = 0; cp < 4; cp++)
#pragma unroll
        for (int p = 0; p < 4; p++) acc[cp][p] = 0ULL;

    prefetch(0);
    CP_COMMIT();

    for (int gc = 0; gc < n_gc; gc++) {
        const int buf = gc & 1;
        float* sx = smem_dyn + buf * BUF_FLOATS;
        float* sw = sx + SX_FLOATS;

        if (gc + 1 < n_gc) {
            prefetch(gc + 1);
            CP_COMMIT();
            CP_WAIT_1();
        } else {
            CP_WAIT_0();
        }
        __syncthreads();

        // ---- main accumulation (identical order to R4) ----
        for (int ci = 0; ci < CIN_CHUNK; ci++) {
#pragma unroll
            for (int kh = 0; kh < 3; kh++) {
                const float* xr =
                    &sx[ci * (SX_ROWS * SX_PITCH) + (h_loc + kh) * SX_PITCH + w0];
                float4 xa = *reinterpret_cast<const float4*>(xr);
                float2 xc = *reinterpret_cast<const float2*>(xr + 4);
                unsigned long long xd[6];
                xd[0] = pack2(xa.x, xa.x);
                xd[1] = pack2(xa.y, xa.y);
                xd[2] = pack2(xa.z, xa.z);
                xd[3] = pack2(xa.w, xa.w);
                xd[4] = pack2(xc.x, xc.x);
                xd[5] = pack2(xc.y, xc.y);
#pragma unroll
                for (int kw = 0; kw < 3; kw++) {
                    const ulonglong2* wp = reinterpret_cast<const ulonglong2*>(
                        &sw[(ci * 9 + kh * 3 + kw) * 32 + co_grp * 8]);
                    ulonglong2 wA = wp[0];
                    ulonglong2 wB = wp[1];
                    unsigned long long wq0 = wA.x, wq1 = wA.y,
                                       wq2 = wB.x, wq3 = wB.y;
#pragma unroll
                    for (int p = 0; p < 4; p++) {
                        ffma2(acc[0][p], wq0, xd[kw + p]);
                        ffma2(acc[1][p], wq1, xd[kw + p]);
                        ffma2(acc[2][p], wq2, xd[kw + p]);
                        ffma2(acc[3][p], wq3, xd[kw + p]);
                    }
                }
            }
        }

        // ---- epilogue at the end of each t-step ----
        if ((gc & 3) == 3) {
            const int tile_id = (gc >> 4) ? (bid + GRID_CTAS) : bid;
            int b, cout0, h0;
            decode_tile(tile_id, b, cout0, h0);
            const int t    = (gc >> 2) & 3;
            const int myc0 = cout0 + co_grp * 8;
            float* ob = out + ((size_t)(t * BATCH + b) * COUT) * (HH * WW)
                            + (h0 + h_loc) * WW + w0;
#pragma unroll
            for (int cp = 0; cp < 4; cp++) {
                const int cl0 = 2 * cp, cl1 = 2 * cp + 1;
                const float a0 = g_alpha[myc0 + cl0], b0 = g_beta[myc0 + cl0];
                const float a1 = g_alpha[myc0 + cl1], b1 = g_beta[myc0 + cl1];
                float sp0[4], sp1[4];
#pragma unroll
                for (int p = 0; p < 4; p++) {
                    float lo, hi;
                    unpack2(acc[cp][p], lo, hi);
                    float y0 = lo * a0 + b0;
                    float y1 = hi * a1 + b1;
                    float m0 = mem[cl0][p] * TAU + y0;
                    float m1 = mem[cl1][p] * TAU + y1;
                    float k0 = (m0 > THRESH) ? 1.f : 0.f;
                    float k1 = (m1 > THRESH) ? 1.f : 0.f;
                    mem[cl0][p] = (k0 != 0.f) ? 0.f : m0;
                    mem[cl1][p] = (k1 != 0.f) ? 0.f : m1;
                    sp0[p] = k0;
                    sp1[p] = k1;
                }
                *reinterpret_cast<float4*>(ob + (size_t)(myc0 + cl0) * (HH * WW)) =
                    make_float4(sp0[0], sp0[1], sp0[2], sp0[3]);
                *reinterpret_cast<float4*>(ob + (size_t)(myc0 + cl1) * (HH * WW)) =
                    make_float4(sp1[0], sp1[1], sp1[2], sp1[3]);
            }
#pragma unroll
            for (int cp = 0; cp < 4; cp++)
#pragma unroll
                for (int p = 0; p < 4; p++) acc[cp][p] = 0ULL;

            if ((gc & 15) == 15) {   // tile boundary: reset LIF membrane
#pragma unroll
                for (int c = 0; c < 8; c++)
#pragma unroll
                    for (int p = 0; p < 4; p++) mem[c][p] = 0.f;
            }
        }

        __syncthreads();
    }
}

extern "C" void kernel_launch(void* const* d_in, const int* in_sizes, int n_in,
                              void* d_out, int out_size) {
    (void)in_sizes; (void)n_in; (void)out_size;
    const float* x      = (const float*)d_in[0];
    const float* conv_w = (const float*)d_in[1];
    const float* conv_b = (const float*)d_in[2];
    const float* bng    = (const float*)d_in[3];
    const float* bnb    = (const float*)d_in[4];
    const float* bnm    = (const float*)d_in[5];
    const float* bnv    = (const float*)d_in[6];
    float* out = (float*)d_out;

    static int attr_done = 0;
    if (!attr_done) {
        cudaFuncSetAttribute(conv_lif_kernel,
                             cudaFuncAttributeMaxDynamicSharedMemorySize,
                             SMEM_BYTES);
        attr_done = 1;
    }

    prep_kernel<<<72, 256>>>(conv_w, conv_b, bng, bnb, bnm, bnv);

    conv_lif_kernel<<<GRID_CTAS, 256, SMEM_BYTES>>>(x, out);
}

// round 6
// speedup vs baseline: 1.2808x; 1.0176x over previous
#include <cuda_runtime.h>
#include <cuda_bf16.h>

// Problem constants
#define T_STEPS 4
#define BATCH   64
#define CIN     64
#define COUT    128
#define HH      32
#define WW      32
#define TAU     0.5f
#define THRESH  1.0f
#define BN_EPS  1e-5f

// Scratch: transposed weights [cin*9][cout] + folded BN affine
__device__ float g_wT[CIN * 9 * COUT];
__device__ float g_alpha[COUT];
__device__ float g_beta[COUT];

// ---------- f32x2 packed helpers ----------
__device__ __forceinline__ unsigned long long pack2(float lo, float hi) {
    unsigned long long r;
    asm("mov.b64 %0, {%1, %2};" : "=l"(r) : "f"(lo), "f"(hi));
    return r;
}
__device__ __forceinline__ void unpack2(unsigned long long v, float& lo, float& hi) {
    asm("mov.b64 {%0, %1}, %2;" : "=f"(lo), "=f"(hi) : "l"(v));
}
__device__ __forceinline__ void ffma2(unsigned long long& d,
                                      unsigned long long a,
                                      unsigned long long b) {
    asm("fma.rn.f32x2 %0, %1, %2, %3;" : "=l"(d) : "l"(a), "l"(b), "l"(d));
}

// ---------- cp.async helpers ----------
__device__ __forceinline__ void cp_async4(unsigned dst, const void* src, int bytes) {
    asm volatile("cp.async.ca.shared.global [%0], [%1], 4, %2;"
                 :: "r"(dst), "l"(src), "r"(bytes));
}
__device__ __forceinline__ void cp_async16(unsigned dst, const void* src) {
    asm volatile("cp.async.cg.shared.global [%0], [%1], 16;"
                 :: "r"(dst), "l"(src));
}
#define CP_COMMIT()  asm volatile("cp.async.commit_group;" ::: "memory")
#define CP_WAIT_0()  asm volatile("cp.async.wait_group 0;" ::: "memory")

// ---------- prep: weight transpose + BN fold ----------
__global__ void prep_kernel(const float* __restrict__ w,
                            const float* __restrict__ cb,
                            const float* __restrict__ gamma,
                            const float* __restrict__ beta,
                            const float* __restrict__ mean,
                            const float* __restrict__ var) {
    int idx = blockIdx.x * blockDim.x + threadIdx.x;
    int stride = gridDim.x * blockDim.x;
    for (int i = idx; i < CIN * 9 * COUT; i += stride) {
        int co = i & (COUT - 1);
        int r  = i >> 7;
        g_wT[i] = w[co * (CIN * 9) + r];
    }
    if (idx < COUT) {
        float inv = rsqrtf(var[idx] + BN_EPS);
        float sc  = gamma[idx] * inv;
        g_alpha[idx] = sc;
        g_beta[idx]  = beta[idx] - mean[idx] * sc + cb[idx] * sc;
    }
}

// ---------- fused conv3x3 + BN + LIF ----------
// Double-buffered, single-barrier-per-chunk, prefetch interleaved mid-compute.
#define CIN_CHUNK 16
#define SX_ROWS   10
#define SX_PITCH  36
#define SX_FLOATS (CIN_CHUNK * SX_ROWS * SX_PITCH)   // 5760
#define SW_FLOATS (CIN_CHUNK * 9 * 32)               // 4608
#define BUF_FLOATS (SX_FLOATS + SW_FLOATS)           // 10368
#define SMEM_BYTES (2 * BUF_FLOATS * 4)              // 82944

#define N_CHUNKS_PER_TILE (T_STEPS * (CIN / CIN_CHUNK))   // 16
#define N_TILES  (BATCH * (COUT / 32) * (HH / 8))         // 1024
#define GRID_CTAS 888
#define EXTRA_CTAS (N_TILES - GRID_CTAS)                  // 136

__device__ __forceinline__ void decode_tile(int tile_id, int& b, int& cout0, int& h0) {
    b     = tile_id >> 4;
    int r = tile_id & 15;
    cout0 = (r >> 2) * 32;
    h0    = (r & 3) * 8;
}

// One (ci,kh)-range compute slab, accumulation order identical to R4/R5.
__device__ __forceinline__ void compute_slab(
    const float* __restrict__ sx, const float* __restrict__ sw,
    int ci_lo, int ci_hi, int h_loc, int w0, int co_grp,
    unsigned long long acc[4][4]) {
    for (int ci = ci_lo; ci < ci_hi; ci++) {
#pragma unroll
        for (int kh = 0; kh < 3; kh++) {
            const float* xr =
                &sx[ci * (SX_ROWS * SX_PITCH) + (h_loc + kh) * SX_PITCH + w0];
            float4 xa = *reinterpret_cast<const float4*>(xr);
            float4 xb4 = *reinterpret_cast<const float4*>(xr + 4);  // conflict-free
            unsigned long long xd[6];
            xd[0] = pack2(xa.x, xa.x);
            xd[1] = pack2(xa.y, xa.y);
            xd[2] = pack2(xa.z, xa.z);
            xd[3] = pack2(xa.w, xa.w);
            xd[4] = pack2(xb4.x, xb4.x);
            xd[5] = pack2(xb4.y, xb4.y);
#pragma unroll
            for (int kw = 0; kw < 3; kw++) {
                const ulonglong2* wp = reinterpret_cast<const ulonglong2*>(
                    &sw[(ci * 9 + kh * 3 + kw) * 32 + co_grp * 8]);
                ulonglong2 wA = wp[0];
                ulonglong2 wB = wp[1];
                unsigned long long wq0 = wA.x, wq1 = wA.y,
                                   wq2 = wB.x, wq3 = wB.y;
#pragma unroll
                for (int p = 0; p < 4; p++) {
                    ffma2(acc[0][p], wq0, xd[kw + p]);
                    ffma2(acc[1][p], wq1, xd[kw + p]);
                    ffma2(acc[2][p], wq2, xd[kw + p]);
                    ffma2(acc[3][p], wq3, xd[kw + p]);
                }
            }
        }
    }
}

__global__ __launch_bounds__(256, 2)
void conv_lif_kernel(const float* __restrict__ x, float* __restrict__ out) {
    extern __shared__ __align__(16) float smem_dyn[];

    const int bid = blockIdx.x;
    const int ntiles = (bid < EXTRA_CTAS) ? 2 : 1;
    const int n_gc = ntiles * N_CHUNKS_PER_TILE;

    const int tid    = threadIdx.x;
    const int w_grp  = tid & 7;
    const int h_loc  = (tid >> 3) & 7;
    const int co_grp = tid >> 6;
    const int w0     = w_grp * 4;

    const unsigned smem_u32 = (unsigned)__cvta_generic_to_shared(smem_dyn);

    auto prefetch = [&](int gc) {
        const int tile_id = (gc >> 4) ? (bid + GRID_CTAS) : bid;
        int b, cout0, h0;
        decode_tile(tile_id, b, cout0, h0);
        const int tc = gc & 15;
        const int t  = tc >> 2;
        const int c0 = (tc & 3) * CIN_CHUNK;
        const int buf = gc & 1;
        const unsigned sx_base = smem_u32 + (unsigned)(buf * BUF_FLOATS) * 4u;
        const unsigned sw_base = sx_base + SX_FLOATS * 4u;
        const float* xb = x + (((t * BATCH + b) * CIN + c0) * (HH * WW));
        for (int e = tid; e < CIN_CHUNK * SX_ROWS * 34; e += 256) {
            int ci  = e / (SX_ROWS * 34);
            int rem = e - ci * (SX_ROWS * 34);
            int r   = rem / 34;
            int c   = rem - r * 34;
            int gh  = h0 - 1 + r;
            int gw  = c - 1;
            bool valid = ((unsigned)gh < (unsigned)HH) && ((unsigned)gw < (unsigned)WW);
            const float* src = valid ? (xb + ci * (HH * WW) + gh * WW + gw) : xb;
            unsigned dst = sx_base +
                (unsigned)(ci * (SX_ROWS * SX_PITCH) + r * SX_PITCH + c) * 4u;
            cp_async4(dst, src, valid ? 4 : 0);
        }
        const float* wb = g_wT + c0 * 9 * COUT + cout0;
        for (int e = tid; e < SW_FLOATS / 4; e += 256) {
            int co4 = e & 7;
            int rk  = e >> 3;
            unsigned dst = sw_base + (unsigned)(rk * 32 + co4 * 4) * 4u;
            cp_async16(dst, wb + rk * COUT + co4 * 4);
        }
    };

    float mem[8][4];
#pragma unroll
    for (int c = 0; c < 8; c++)
#pragma unroll
        for (int p = 0; p < 4; p++) mem[c][p] = 0.f;

    unsigned long long acc[4][4];
#pragma unroll
    for (int cp = 0; cp < 4; cp++)
#pragma unroll
        for (int p = 0; p < 4; p++) acc[cp][p] = 0ULL;

    // prime: chunk 0 must be resident before the first compute
    prefetch(0);
    CP_COMMIT();
    CP_WAIT_0();
    __syncthreads();

    for (int gc = 0; gc < n_gc; gc++) {
        const int buf = gc & 1;
        const float* sx = smem_dyn + buf * BUF_FLOATS;
        const float* sw = sx + SX_FLOATS;
        const bool have_next = (gc + 1 < n_gc);

        // head of compute drains while warps stagger into prefetch
        compute_slab(sx, sw, 0, 3, h_loc, w0, co_grp, acc);

        if (have_next) {
            prefetch(gc + 1);
            CP_COMMIT();
        }

        compute_slab(sx, sw, 3, CIN_CHUNK, h_loc, w0, co_grp, acc);

        // ---- epilogue at the end of each t-step ----
        if ((gc & 3) == 3) {
            const int tile_id = (gc >> 4) ? (bid + GRID_CTAS) : bid;
            int b, cout0, h0;
            decode_tile(tile_id, b, cout0, h0);
            const int t    = (gc >> 2) & 3;
            const int myc0 = cout0 + co_grp * 8;
            float* ob = out + ((size_t)(t * BATCH + b) * COUT) * (HH * WW)
                            + (h0 + h_loc) * WW + w0;
#pragma unroll
            for (int cp = 0; cp < 4; cp++) {
                const int cl0 = 2 * cp, cl1 = 2 * cp + 1;
                const float a0 = g_alpha[myc0 + cl0], b0 = g_beta[myc0 + cl0];
                const float a1 = g_alpha[myc0 + cl1], b1 = g_beta[myc0 + cl1];
                float sp0[4], sp1[4];
#pragma unroll
                for (int p = 0; p < 4; p++) {
                    float lo, hi;
                    unpack2(acc[cp][p], lo, hi);
                    float y0 = lo * a0 + b0;
                    float y1 = hi * a1 + b1;
                    float m0 = mem[cl0][p] * TAU + y0;
                    float m1 = mem[cl1][p] * TAU + y1;
                    float k0 = (m0 > THRESH) ? 1.f : 0.f;
                    float k1 = (m1 > THRESH) ? 1.f : 0.f;
                    mem[cl0][p] = (k0 != 0.f) ? 0.f : m0;
                    mem[cl1][p] = (k1 != 0.f) ? 0.f : m1;
                    sp0[p] = k0;
                    sp1[p] = k1;
                }
                *reinterpret_cast<float4*>(ob + (size_t)(myc0 + cl0) * (HH * WW)) =
                    make_float4(sp0[0], sp0[1], sp0[2], sp0[3]);
                *reinterpret_cast<float4*>(ob + (size_t)(myc0 + cl1) * (HH * WW)) =
                    make_float4(sp1[0], sp1[1], sp1[2], sp1[3]);
            }
#pragma unroll
            for (int cp = 0; cp < 4; cp++)
#pragma unroll
                for (int p = 0; p < 4; p++) acc[cp][p] = 0ULL;

            if ((gc & 15) == 15) {   // tile boundary: reset LIF membrane
#pragma unroll
                for (int c = 0; c < 8; c++)
#pragma unroll
                    for (int p = 0; p < 4; p++) mem[c][p] = 0.f;
            }
        }

        if (have_next) CP_WAIT_0();
        // single barrier: publishes chunk gc+1's data AND releases buf^1 for
        // the prefetch issued in iteration gc+1.
        __syncthreads();
    }
}

extern "C" void kernel_launch(void* const* d_in, const int* in_sizes, int n_in,
                              void* d_out, int out_size) {
    (void)in_sizes; (void)n_in; (void)out_size;
    const float* x      = (const float*)d_in[0];
    const float* conv_w = (const float*)d_in[1];
    const float* conv_b = (const float*)d_in[2];
    const float* bng    = (const float*)d_in[3];
    const float* bnb    = (const float*)d_in[4];
    const float* bnm    = (const float*)d_in[5];
    const float* bnv    = (const float*)d_in[6];
    float* out = (float*)d_out;

    static int attr_done = 0;
    if (!attr_done) {
        cudaFuncSetAttribute(conv_lif_kernel,
                             cudaFuncAttributeMaxDynamicSharedMemorySize,
                             SMEM_BYTES);
        attr_done = 1;
    }

    prep_kernel<<<72, 256>>>(conv_w, conv_b, bng, bnb, bnm, bnv);

    conv_lif_kernel<<<GRID_CTAS, 256, SMEM_BYTES>>>(x, out);
}

// round 7
// speedup vs baseline: 1.3829x; 1.0797x over previous
#include <cuda_runtime.h>
#include <cuda_bf16.h>

// Problem constants
#define T_STEPS 4
#define BATCH   64
#define CIN     64
#define COUT    128
#define HH      32
#define WW      32
#define TAU     0.5f
#define THRESH  1.0f
#define BN_EPS  1e-5f

// Scratch: transposed weights [cin*9][cout] + folded BN affine
__device__ float g_wT[CIN * 9 * COUT];
__device__ float g_alpha[COUT];
__device__ float g_beta[COUT];

// ---------- f32x2 packed helpers ----------
__device__ __forceinline__ unsigned long long pack2(float lo, float hi) {
    unsigned long long r;
    asm("mov.b64 %0, {%1, %2};" : "=l"(r) : "f"(lo), "f"(hi));
    return r;
}
__device__ __forceinline__ void unpack2(unsigned long long v, float& lo, float& hi) {
    asm("mov.b64 {%0, %1}, %2;" : "=f"(lo), "=f"(hi) : "l"(v));
}
__device__ __forceinline__ void ffma2(unsigned long long& d,
                                      unsigned long long a,
                                      unsigned long long b) {
    asm("fma.rn.f32x2 %0, %1, %2, %3;" : "=l"(d) : "l"(a), "l"(b), "l"(d));
}

// ---------- cp.async helpers ----------
__device__ __forceinline__ void cp_async4(unsigned dst, const void* src, int bytes) {
    asm volatile("cp.async.ca.shared.global [%0], [%1], 4, %2;"
                 :: "r"(dst), "l"(src), "r"(bytes));
}
__device__ __forceinline__ void cp_async16(unsigned dst, const void* src) {
    asm volatile("cp.async.cg.shared.global [%0], [%1], 16;"
                 :: "r"(dst), "l"(src));
}
#define CP_COMMIT()  asm volatile("cp.async.commit_group;" ::: "memory")
#define CP_WAIT_0()  asm volatile("cp.async.wait_group 0;" ::: "memory")

// ---------- prep: weight transpose + BN fold ----------
__global__ void prep_kernel(const float* __restrict__ w,
                            const float* __restrict__ cb,
                            const float* __restrict__ gamma,
                            const float* __restrict__ beta,
                            const float* __restrict__ mean,
                            const float* __restrict__ var) {
    int idx = blockIdx.x * blockDim.x + threadIdx.x;
    int stride = gridDim.x * blockDim.x;
    for (int i = idx; i < CIN * 9 * COUT; i += stride) {
        int co = i & (COUT - 1);
        int r  = i >> 7;
        g_wT[i] = w[co * (CIN * 9) + r];
    }
    if (idx < COUT) {
        float inv = rsqrtf(var[idx] + BN_EPS);
        float sc  = gamma[idx] * inv;
        g_alpha[idx] = sc;
        g_beta[idx]  = beta[idx] - mean[idx] * sc + cb[idx] * sc;
    }
}

// ---------- fused conv3x3 + BN + LIF ----------
// Double-buffered, single-barrier-per-chunk, per-warp-staggered prefetch.
#define CIN_CHUNK 16
#define SX_ROWS   10
#define SX_PITCH  36
#define SX_FLOATS (CIN_CHUNK * SX_ROWS * SX_PITCH)   // 5760
#define SW_FLOATS (CIN_CHUNK * 9 * 32)               // 4608
#define BUF_FLOATS (SX_FLOATS + SW_FLOATS)           // 10368
#define AB_FLOATS  (2 * COUT)                        // 256 (alpha|beta)
#define SMEM_BYTES ((2 * BUF_FLOATS + AB_FLOATS) * 4)   // 83968

#define N_CHUNKS_PER_TILE (T_STEPS * (CIN / CIN_CHUNK))   // 16
#define N_TILES  (BATCH * (COUT / 32) * (HH / 8))         // 1024
#define GRID_CTAS 888
#define EXTRA_CTAS (N_TILES - GRID_CTAS)                  // 136

__device__ __forceinline__ void decode_tile(int tile_id, int& b, int& cout0, int& h0) {
    b     = tile_id >> 4;
    int r = tile_id & 15;
    cout0 = (r >> 2) * 32;
    h0    = (r & 3) * 8;
}

// One ci of accumulation; order identical to R4/R5/R6.
__device__ __forceinline__ void compute_ci(
    const float* __restrict__ sx, const float* __restrict__ sw,
    int ci, int h_loc, int w0, int co_grp,
    unsigned long long acc[4][4]) {
#pragma unroll
    for (int kh = 0; kh < 3; kh++) {
        const float* xr =
            &sx[ci * (SX_ROWS * SX_PITCH) + (h_loc + kh) * SX_PITCH + w0];
        float4 xa  = *reinterpret_cast<const float4*>(xr);
        float4 xb4 = *reinterpret_cast<const float4*>(xr + 4);
        unsigned long long xd[6];
        xd[0] = pack2(xa.x, xa.x);
        xd[1] = pack2(xa.y, xa.y);
        xd[2] = pack2(xa.z, xa.z);
        xd[3] = pack2(xa.w, xa.w);
        xd[4] = pack2(xb4.x, xb4.x);
        xd[5] = pack2(xb4.y, xb4.y);
#pragma unroll
        for (int kw = 0; kw < 3; kw++) {
            const ulonglong2* wp = reinterpret_cast<const ulonglong2*>(
                &sw[(ci * 9 + kh * 3 + kw) * 32 + co_grp * 8]);
            ulonglong2 wA = wp[0];
            ulonglong2 wB = wp[1];
            unsigned long long wq0 = wA.x, wq1 = wA.y,
                               wq2 = wB.x, wq3 = wB.y;
#pragma unroll
            for (int p = 0; p < 4; p++) {
                ffma2(acc[0][p], wq0, xd[kw + p]);
                ffma2(acc[1][p], wq1, xd[kw + p]);
                ffma2(acc[2][p], wq2, xd[kw + p]);
                ffma2(acc[3][p], wq3, xd[kw + p]);
            }
        }
    }
}

__global__ __launch_bounds__(256, 2)
void conv_lif_kernel(const float* __restrict__ x, float* __restrict__ out) {
    extern __shared__ __align__(16) float smem_dyn[];
    float* s_ab = smem_dyn + 2 * BUF_FLOATS;   // [0..127]=alpha, [128..255]=beta

    const int bid = blockIdx.x;
    const int ntiles = (bid < EXTRA_CTAS) ? 2 : 1;
    const int n_gc = ntiles * N_CHUNKS_PER_TILE;

    const int tid    = threadIdx.x;
    const int w_grp  = tid & 7;
    const int h_loc  = (tid >> 3) & 7;
    const int co_grp = tid >> 6;
    const int w0     = w_grp * 4;
    const int my_slot = 2 + (tid >> 5);        // warp-staggered: ci slots 2..9

    const unsigned smem_u32 = (unsigned)__cvta_generic_to_shared(smem_dyn);

    // Per-thread share of the prefetch for global chunk gc.
    // x main body only: 16ci x 10r x 32c (cols c_smem 1..32); halo cols 0,33
    // are constant zero (initialized once, never reloaded).
    auto prefetch_share = [&](int gc) {
        const int tile_id = (gc >> 4) ? (bid + GRID_CTAS) : bid;
        int b, cout0, h0;
        decode_tile(tile_id, b, cout0, h0);
        const int tc = gc & 15;
        const int t  = tc >> 2;
        const int c0 = (tc & 3) * CIN_CHUNK;
        const int buf = gc & 1;
        const unsigned sx_base = smem_u32 + (unsigned)(buf * BUF_FLOATS) * 4u;
        const unsigned sw_base = sx_base + SX_FLOATS * 4u;
        const float* xb = x + (((t * BATCH + b) * CIN + c0) * (HH * WW));
        const unsigned c    = (unsigned)tid & 31u;
        const unsigned rg0  = (unsigned)tid >> 5;
#pragma unroll
        for (int k = 0; k < 20; k++) {
            unsigned rowg = rg0 + 8u * k;      // 0..159
            unsigned ci   = rowg / 10u;
            unsigned r    = rowg - ci * 10u;
            int gh = h0 - 1 + (int)r;
            bool valid = (unsigned)gh < (unsigned)HH;
            const float* src = xb + ci * (HH * WW) + (valid ? gh : 0) * WW + c;
            unsigned dst = sx_base +
                (unsigned)(ci * (SX_ROWS * SX_PITCH) + r * SX_PITCH + c + 1u) * 4u;
            cp_async4(dst, src, valid ? 4 : 0);
        }
        const float* wb = g_wT + c0 * 9 * COUT + cout0;
#pragma unroll
        for (int k = 0; k < 5; k++) {
            int e = tid + k * 256;
            if (e < SW_FLOATS / 4) {
                int co4 = e & 7;
                int rk  = e >> 3;
                unsigned dst = sw_base + (unsigned)(rk * 32 + co4 * 4) * 4u;
                cp_async16(dst, wb + rk * COUT + co4 * 4);
            }
        }
    };

    // ---- one-time init: alpha/beta -> smem, zero halo cols of both buffers ----
    for (int e = tid; e < COUT; e += 256) {
        s_ab[e]        = g_alpha[e];
        s_ab[COUT + e] = g_beta[e];
    }
    for (int e = tid; e < 2 * CIN_CHUNK * SX_ROWS * 2; e += 256) {  // 640
        int buf = e & 1;
        int q   = e >> 1;                 // 0..319
        int col = (q & 1) ? 33 : 0;
        int rw  = q >> 1;                 // 0..159
        int ci  = rw / SX_ROWS;
        int r   = rw - ci * SX_ROWS;
        smem_dyn[buf * BUF_FLOATS + ci * (SX_ROWS * SX_PITCH) + r * SX_PITCH + col] = 0.f;
    }

    float mem[8][4];
#pragma unroll
    for (int c = 0; c < 8; c++)
#pragma unroll
        for (int p = 0; p < 4; p++) mem[c][p] = 0.f;

    unsigned long long acc[4][4];
#pragma unroll
    for (int cp = 0; cp < 4; cp++)
#pragma unroll
        for (int p = 0; p < 4; p++) acc[cp][p] = 0ULL;

    // prime: chunk 0 resident before first compute
    prefetch_share(0);
    CP_COMMIT();
    CP_WAIT_0();
    __syncthreads();

    for (int gc = 0; gc < n_gc; gc++) {
        const int buf = gc & 1;
        const float* sx = smem_dyn + buf * BUF_FLOATS;
        const float* sw = sx + SX_FLOATS;
        const bool have_next = (gc + 1 < n_gc);

        for (int ci = 0; ci < CIN_CHUNK; ci++) {
            compute_ci(sx, sw, ci, h_loc, w0, co_grp, acc);
            if (have_next && ci == my_slot) {   // warp-uniform branch
                prefetch_share(gc + 1);
                CP_COMMIT();
            }
        }

        // ---- epilogue at the end of each t-step ----
        if ((gc & 3) == 3) {
            const int tile_id = (gc >> 4) ? (bid + GRID_CTAS) : bid;
            int b, cout0, h0;
            decode_tile(tile_id, b, cout0, h0);
            const int t    = (gc >> 2) & 3;
            const int myc0 = cout0 + co_grp * 8;
            float* ob = out + ((size_t)(t * BATCH + b) * COUT) * (HH * WW)
                            + (h0 + h_loc) * WW + w0;
#pragma unroll
            for (int cp = 0; cp < 4; cp++) {
                const int cl0 = 2 * cp, cl1 = 2 * cp + 1;
                const float a0 = s_ab[myc0 + cl0], b0 = s_ab[COUT + myc0 + cl0];
                const float a1 = s_ab[myc0 + cl1], b1 = s_ab[COUT + myc0 + cl1];
                float sp0[4], sp1[4];
#pragma unroll
                for (int p = 0; p < 4; p++) {
                    float lo, hi;
                    unpack2(acc[cp][p], lo, hi);
                    float y0 = lo * a0 + b0;
                    float y1 = hi * a1 + b1;
                    float m0 = mem[cl0][p] * TAU + y0;
                    float m1 = mem[cl1][p] * TAU + y1;
                    float k0 = (m0 > THRESH) ? 1.f : 0.f;
                    float k1 = (m1 > THRESH) ? 1.f : 0.f;
                    mem[cl0][p] = (k0 != 0.f) ? 0.f : m0;
                    mem[cl1][p] = (k1 != 0.f) ? 0.f : m1;
                    sp0[p] = k0;
                    sp1[p] = k1;
                }
                *reinterpret_cast<float4*>(ob + (size_t)(myc0 + cl0) * (HH * WW)) =
                    make_float4(sp0[0], sp0[1], sp0[2], sp0[3]);
                *reinterpret_cast<float4*>(ob + (size_t)(myc0 + cl1) * (HH * WW)) =
                    make_float4(sp1[0], sp1[1], sp1[2], sp1[3]);
            }
#pragma unroll
            for (int cp = 0; cp < 4; cp++)
#pragma unroll
                for (int p = 0; p < 4; p++) acc[cp][p] = 0ULL;

            if ((gc & 15) == 15) {   // tile boundary: reset LIF membrane
#pragma unroll
                for (int c = 0; c < 8; c++)
#pragma unroll
                    for (int p = 0; p < 4; p++) mem[c][p] = 0.f;
            }
        }

        if (have_next) CP_WAIT_0();
        // single barrier: publishes chunk gc+1's data AND releases buf^1 for
        // the prefetch issued during iteration gc+1.
        __syncthreads();
    }
}

extern "C" void kernel_launch(void* const* d_in, const int* in_sizes, int n_in,
                              void* d_out, int out_size) {
    (void)in_sizes; (void)n_in; (void)out_size;
    const float* x      = (const float*)d_in[0];
    const float* conv_w = (const float*)d_in[1];
    const float* conv_b = (const float*)d_in[2];
    const float* bng    = (const float*)d_in[3];
    const float* bnb    = (const float*)d_in[4];
    const float* bnm    = (const float*)d_in[5];
    const float* bnv    = (const float*)d_in[6];
    float* out = (float*)d_out;

    static int attr_done = 0;
    if (!attr_done) {
        cudaFuncSetAttribute(conv_lif_kernel,
                             cudaFuncAttributeMaxDynamicSharedMemorySize,
                             SMEM_BYTES);
        attr_done = 1;
    }

    prep_kernel<<<72, 256>>>(conv_w, conv_b, bng, bnb, bnm, bnv);

    conv_lif_kernel<<<GRID_CTAS, 256, SMEM_BYTES>>>(x, out);
}